// round 12
// baseline (speedup 1.0000x reference)
#include <cuda_runtime.h>
#include <math.h>

// Problem constants: B=4, N=207, L=96, H=8, E=64
#define L_LEN   96
#define H_NUM   8
#define E_DIM   64
#define NBN     828            // B*N
#define TOT     40697856       // B*N*L*H*E
#define THREADS 128
#define TAU_PER 24             // tau values per thread (4 groups of 24 = 96)

#define SMEM_ULL   (3072 + 6144)       // q: 96*32 f32x2, k_ext: 192*32 f32x2
#define SMEM_BYTES (SMEM_ULL * 8)      // 73728 bytes

// Packed fp32x2 FMA (Blackwell sm_100+): one instruction, two fp32 FMAs.
__device__ __forceinline__ unsigned long long fma2(unsigned long long a,
                                                   unsigned long long b,
                                                   unsigned long long c) {
    unsigned long long d;
    asm("fma.rn.f32x2 %0, %1, %2, %3;" : "=l"(d) : "l"(a), "l"(b), "l"(c));
    return d;
}
__device__ __forceinline__ float lo2(unsigned long long a) {
    return __uint_as_float((unsigned int)(a & 0xffffffffull));
}
__device__ __forceinline__ float hi2(unsigned long long a) {
    return __uint_as_float((unsigned int)(a >> 32));
}

// Insert (v, idx) into a descending top-4 list. Strict '>' keeps the earlier
// (lower-tau) entry on exact ties, matching top_k's first-occurrence rule.
__device__ __forceinline__ void ins4(float v, int idx, float* tv, int* ti) {
#pragma unroll
    for (int s = 0; s < 4; s++) {
        if (v > tv[s]) {
            float tf = tv[s]; tv[s] = v; v = tf;
            int   tt = ti[s]; ti[s] = idx; idx = tt;
        }
    }
}

__global__ __launch_bounds__(THREADS, 3)
void autocorr_kernel(const float* __restrict__ gq,
                     const float* __restrict__ gk,
                     const float* __restrict__ gv,
                     float* __restrict__ outV,
                     float* __restrict__ outC) {
    extern __shared__ unsigned long long smem[];
    unsigned long long* sm_q = smem;          // [l][pair]   : 96 x 32 f32x2 (later reused for v)
    unsigned long long* sm_k = smem + 3072;   // [idx][pair] : 192 x 32 f32x2 (k duplicated, wrap-free)

    const int tid  = threadIdx.x;
    const int pair = tid & 31;     // e-pair: e = 2*pair, 2*pair+1
    const int grp  = tid >> 5;     // tau group 0..3
    const int bn   = blockIdx.x >> 3;
    const int h    = blockIdx.x & 7;

    // Base offset in f32x2 units for this (bn, h): layout [bn][l][h][e]
    const long long base2 = (long long)bn * (L_LEN * H_NUM * E_DIM / 2) + h * (E_DIM / 2);
    const unsigned long long* q2 = (const unsigned long long*)gq + base2;
    const unsigned long long* k2 = (const unsigned long long*)gk + base2;
    const unsigned long long* v2 = (const unsigned long long*)gv + base2;

    // ---- Phase 0: stage q and k (duplicated k_ext[j] = k[j mod 96]) ----
#pragma unroll 4
    for (int i = tid; i < 96 * 32; i += THREADS) {
        const int l = i >> 5, p = i & 31;
        sm_q[i] = q2[(long long)l * 256 + p];
        const unsigned long long kv = k2[(long long)l * 256 + p];
        sm_k[i]        = kv;
        sm_k[i + 3072] = kv;
    }
    __syncthreads();

    // ---- Phase 1: corr[tau] = sum_t q[t] * k_ext[t - tau + 96] ----
    const int tau0 = grp * TAU_PER;
    unsigned long long acc[TAU_PER];
#pragma unroll
    for (int j = 0; j < TAU_PER; j++) acc[j] = 0ull;

    const unsigned long long* qs = sm_q + pair;
    const unsigned long long* ks = sm_k + pair;

    for (int t0 = 0; t0 < L_LEN; t0 += 8) {
        unsigned long long qr[8];
#pragma unroll
        for (int tt = 0; tt < 8; tt++) qr[tt] = qs[(t0 + tt) * 32];

        unsigned long long kr[31];
        const int kb = t0 - tau0 - 23 + 96;   // in [1, 161]; kb+30 <= 191
#pragma unroll
        for (int j = 0; j < 31; j++) kr[j] = ks[(kb + j) * 32];

#pragma unroll
        for (int tt = 0; tt < 8; tt++) {
#pragma unroll
            for (int d = 0; d < TAU_PER; d++) {
                // k_ext index = kb + (tt + 23 - d) = (t0+tt) - (tau0+d) + 96
                acc[d] = fma2(qr[tt], kr[tt + 23 - d], acc[d]);
            }
        }
    }

    // Write corr to global (if requested) and track per-channel top-4 inline.
    float tvA[4] = {-1e30f, -1e30f, -1e30f, -1e30f};
    float tvB[4] = {-1e30f, -1e30f, -1e30f, -1e30f};
    int   tiA[4] = {0, 0, 0, 0}, tiB[4] = {0, 0, 0, 0};

    if (outC) {
        unsigned long long* cbase = (unsigned long long*)outC;
        const long long cOff = base2 + pair;   // ((bn*96+tau)*8+h)*32 + pair
#pragma unroll
        for (int j = 0; j < TAU_PER; j++) {
            cbase[cOff + (long long)(tau0 + j) * 256] = acc[j];
        }
    }
#pragma unroll
    for (int j = 0; j < TAU_PER; j++) {
        ins4(lo2(acc[j]), tau0 + j, tvA, tiA);
        ins4(hi2(acc[j]), tau0 + j, tvB, tiB);
    }

    __syncthreads();   // all reads of sm_q / sm_k done; safe to alias

    // ---- Phase 2: merge top-4 across tau groups, softmax ----
    float* cand_v = (float*)sm_k;             // [grp][e][4]  : 1024 floats
    int*   cand_i = (int*)sm_k + 1024;        // [grp][e][4]  : 1024 ints
    float* wts    = (float*)sm_k + 2048;      // [e][4]       : 256 floats
    int*   dly    = (int*)sm_k + 2304;        // [e][4]       : 256 ints
    {
        const int e0 = 2 * pair, e1 = e0 + 1;
#pragma unroll
        for (int s = 0; s < 4; s++) {
            cand_v[grp * 256 + e0 * 4 + s] = tvA[s];
            cand_i[grp * 256 + e0 * 4 + s] = tiA[s];
            cand_v[grp * 256 + e1 * 4 + s] = tvB[s];
            cand_i[grp * 256 + e1 * 4 + s] = tiB[s];
        }
    }
    __syncthreads();

    if (tid < 64) {
        float tv[4] = {-1e30f, -1e30f, -1e30f, -1e30f};
        int   ti[4] = {0, 0, 0, 0};
#pragma unroll
        for (int g = 0; g < 4; g++)
#pragma unroll
            for (int s = 0; s < 4; s++)
                ins4(cand_v[g * 256 + tid * 4 + s], cand_i[g * 256 + tid * 4 + s], tv, ti);

        const float m = tv[0];
        float ex[4], sum = 0.f;
#pragma unroll
        for (int s = 0; s < 4; s++) { ex[s] = expf(tv[s] - m); sum += ex[s]; }
        const float inv = 1.f / sum;
#pragma unroll
        for (int s = 0; s < 4; s++) { wts[tid * 4 + s] = ex[s] * inv; dly[tid * 4 + s] = ti[s]; }
    }

    // All threads stage v into the dead q buffer (same [l][pair] layout).
#pragma unroll 4
    for (int i = tid; i < 96 * 32; i += THREADS) {
        const int l = i >> 5, p = i & 31;
        sm_q[i] = v2[(long long)l * 256 + p];
    }
    __syncthreads();

    // ---- Phase 3: V[t] = sum_i w_i * v[(t + delay_i) mod 96] ----
    {
        const int e  = tid & 63;
        const int t0 = (tid >> 6) * 48;
        const float w0 = wts[e * 4 + 0], w1 = wts[e * 4 + 1];
        const float w2 = wts[e * 4 + 2], w3 = wts[e * 4 + 3];
        const int   d0 = dly[e * 4 + 0], d1 = dly[e * 4 + 1];
        const int   d2 = dly[e * 4 + 2], d3 = dly[e * 4 + 3];
        const float* vf = (const float*)sm_q;   // scalar view: [l*64 + e]
        float* oV = outV + (long long)bn * (L_LEN * H_NUM * E_DIM) + h * E_DIM + e;

#pragma unroll 4
        for (int t = t0; t < t0 + 48; t++) {
            int r0 = t + d0; if (r0 >= 96) r0 -= 96;
            int r1 = t + d1; if (r1 >= 96) r1 -= 96;
            int r2 = t + d2; if (r2 >= 96) r2 -= 96;
            int r3 = t + d3; if (r3 >= 96) r3 -= 96;
            const float s = w0 * vf[r0 * 64 + e] + w1 * vf[r1 * 64 + e]
                          + w2 * vf[r2 * 64 + e] + w3 * vf[r3 * 64 + e];
            oV[(long long)t * (H_NUM * E_DIM)] = s;
        }
    }
}

extern "C" void kernel_launch(void* const* d_in, const int* in_sizes, int n_in,
                              void* d_out, int out_size) {
    const float* q = (const float*)d_in[0];
    const float* k = (const float*)d_in[1];
    const float* v = (const float*)d_in[2];
    float* out  = (float*)d_out;
    // Reference returns (V, corr_transposed): write both when out buffer holds both.
    float* outC = (out_size >= 2 * TOT) ? (out + TOT) : nullptr;

    cudaFuncSetAttribute(autocorr_kernel,
                         cudaFuncAttributeMaxDynamicSharedMemorySize, SMEM_BYTES);
    autocorr_kernel<<<NBN * H_NUM, THREADS, SMEM_BYTES>>>(q, k, v, out, outC);
}

// round 13
// speedup vs baseline: 1.0366x; 1.0366x over previous
#include <cuda_runtime.h>
#include <math.h>

// Problem constants: B=4, N=207, L=96, H=8, E=64
#define L_LEN   96
#define H_NUM   8
#define E_DIM   64
#define NBN     828            // B*N
#define TOT     40697856       // B*N*L*H*E
#define THREADS 128
#define TAU_PER 24             // tau values per thread (4 groups of 24 = 96)

#define SMEM_ULL   (3072 + 6144)       // q: 96*32 f32x2, k_ext: 192*32 f32x2
#define SMEM_BYTES (SMEM_ULL * 8)      // 73728 bytes

// Packed fp32x2 FMA (Blackwell sm_100+): one instruction, two fp32 FMAs.
__device__ __forceinline__ unsigned long long fma2(unsigned long long a,
                                                   unsigned long long b,
                                                   unsigned long long c) {
    unsigned long long d;
    asm("fma.rn.f32x2 %0, %1, %2, %3;" : "=l"(d) : "l"(a), "l"(b), "l"(c));
    return d;
}
__device__ __forceinline__ float lo2(unsigned long long a) {
    return __uint_as_float((unsigned int)(a & 0xffffffffull));
}
__device__ __forceinline__ float hi2(unsigned long long a) {
    return __uint_as_float((unsigned int)(a >> 32));
}

// Insert (v, idx) into a descending top-4 list. Strict '>' keeps the earlier
// (lower-tau) entry on exact ties, matching top_k's first-occurrence rule.
__device__ __forceinline__ void ins4(float v, int idx, float* tv, int* ti) {
#pragma unroll
    for (int s = 0; s < 4; s++) {
        if (v > tv[s]) {
            float tf = tv[s]; tv[s] = v; v = tf;
            int   tt = ti[s]; ti[s] = idx; idx = tt;
        }
    }
}

__global__ __launch_bounds__(THREADS, 3)
void autocorr_kernel(const float* __restrict__ gq,
                     const float* __restrict__ gk,
                     const float* __restrict__ gv,
                     float* __restrict__ outV,
                     float* __restrict__ outC) {
    extern __shared__ unsigned long long smem[];
    unsigned long long* sm_q = smem;          // [l][pair]   : 96 x 32 f32x2 (later reused for v)
    unsigned long long* sm_k = smem + 3072;   // [idx][pair] : 192 x 32 f32x2 (k duplicated, wrap-free)

    const int tid  = threadIdx.x;
    const int pair = tid & 31;     // e-pair: e = 2*pair, 2*pair+1
    const int grp  = tid >> 5;     // tau group 0..3
    const int bn   = blockIdx.x >> 3;
    const int h    = blockIdx.x & 7;

    // Base offset in f32x2 units for this (bn, h): layout [bn][l][h][e]
    const long long base2 = (long long)bn * (L_LEN * H_NUM * E_DIM / 2) + h * (E_DIM / 2);
    const unsigned long long* q2 = (const unsigned long long*)gq + base2;
    const unsigned long long* k2 = (const unsigned long long*)gk + base2;
    const unsigned long long* v2 = (const unsigned long long*)gv + base2;

    // ---- Phase 0: stage q and k (duplicated k_ext[j] = k[j mod 96]) ----
#pragma unroll 4
    for (int i = tid; i < 96 * 32; i += THREADS) {
        const int l = i >> 5, p = i & 31;
        sm_q[i] = q2[(long long)l * 256 + p];
        const unsigned long long kv = k2[(long long)l * 256 + p];
        sm_k[i]        = kv;
        sm_k[i + 3072] = kv;
    }
    __syncthreads();

    // ---- Phase 1: corr[tau] = sum_t q[t] * k_ext[t - tau + 96] ----
    const int tau0 = grp * TAU_PER;
    unsigned long long acc[TAU_PER];
#pragma unroll
    for (int j = 0; j < TAU_PER; j++) acc[j] = 0ull;

    const unsigned long long* qs = sm_q + pair;
    const unsigned long long* ks = sm_k + pair;

    for (int t0 = 0; t0 < L_LEN; t0 += 8) {
        unsigned long long qr[8];
#pragma unroll
        for (int tt = 0; tt < 8; tt++) qr[tt] = qs[(t0 + tt) * 32];

        unsigned long long kr[31];
        const int kb = t0 - tau0 - 23 + 96;   // in [1, 161]; kb+30 <= 191
#pragma unroll
        for (int j = 0; j < 31; j++) kr[j] = ks[(kb + j) * 32];

#pragma unroll
        for (int tt = 0; tt < 8; tt++) {
#pragma unroll
            for (int d = 0; d < TAU_PER; d++) {
                // k_ext index = kb + (tt + 23 - d) = (t0+tt) - (tau0+d) + 96
                acc[d] = fma2(qr[tt], kr[tt + 23 - d], acc[d]);
            }
        }
    }

    // Write corr to global (if requested) and track per-channel top-4 inline.
    float tvA[4] = {-1e30f, -1e30f, -1e30f, -1e30f};
    float tvB[4] = {-1e30f, -1e30f, -1e30f, -1e30f};
    int   tiA[4] = {0, 0, 0, 0}, tiB[4] = {0, 0, 0, 0};

    if (outC) {
        unsigned long long* cbase = (unsigned long long*)outC;
        const long long cOff = base2 + pair;   // ((bn*96+tau)*8+h)*32 + pair
#pragma unroll
        for (int j = 0; j < TAU_PER; j++) {
            cbase[cOff + (long long)(tau0 + j) * 256] = acc[j];
        }
    }
#pragma unroll
    for (int j = 0; j < TAU_PER; j++) {
        ins4(lo2(acc[j]), tau0 + j, tvA, tiA);
        ins4(hi2(acc[j]), tau0 + j, tvB, tiB);
    }

    __syncthreads();   // all reads of sm_q / sm_k done; safe to alias

    // ---- Phase 2: merge top-4 across tau groups, softmax ----
    float* cand_v = (float*)sm_k;             // [grp][e][4]  : 1024 floats
    int*   cand_i = (int*)sm_k + 1024;        // [grp][e][4]  : 1024 ints
    float* wts    = (float*)sm_k + 2048;      // [e][4]       : 256 floats
    int*   dly    = (int*)sm_k + 2304;        // [e][4]       : 256 ints
    {
        const int e0 = 2 * pair, e1 = e0 + 1;
#pragma unroll
        for (int s = 0; s < 4; s++) {
            cand_v[grp * 256 + e0 * 4 + s] = tvA[s];
            cand_i[grp * 256 + e0 * 4 + s] = tiA[s];
            cand_v[grp * 256 + e1 * 4 + s] = tvB[s];
            cand_i[grp * 256 + e1 * 4 + s] = tiB[s];
        }
    }
    __syncthreads();

    if (tid < 64) {
        float tv[4] = {-1e30f, -1e30f, -1e30f, -1e30f};
        int   ti[4] = {0, 0, 0, 0};
#pragma unroll
        for (int g = 0; g < 4; g++)
#pragma unroll
            for (int s = 0; s < 4; s++)
                ins4(cand_v[g * 256 + tid * 4 + s], cand_i[g * 256 + tid * 4 + s], tv, ti);

        const float m = tv[0];
        float ex[4], sum = 0.f;
#pragma unroll
        for (int s = 0; s < 4; s++) { ex[s] = expf(tv[s] - m); sum += ex[s]; }
        const float inv = 1.f / sum;
#pragma unroll
        for (int s = 0; s < 4; s++) { wts[tid * 4 + s] = ex[s] * inv; dly[tid * 4 + s] = ti[s]; }
    }

    // All threads stage v into the dead q buffer (same [l][pair] layout).
#pragma unroll 4
    for (int i = tid; i < 96 * 32; i += THREADS) {
        const int l = i >> 5, p = i & 31;
        sm_q[i] = v2[(long long)l * 256 + p];
    }
    __syncthreads();

    // ---- Phase 3: V[t] = sum_i w_i * v[(t + delay_i) mod 96] ----
    {
        const int e  = tid & 63;
        const int t0 = (tid >> 6) * 48;
        const float w0 = wts[e * 4 + 0], w1 = wts[e * 4 + 1];
        const float w2 = wts[e * 4 + 2], w3 = wts[e * 4 + 3];
        const int   d0 = dly[e * 4 + 0], d1 = dly[e * 4 + 1];
        const int   d2 = dly[e * 4 + 2], d3 = dly[e * 4 + 3];
        const float* vf = (const float*)sm_q;   // scalar view: [l*64 + e]
        float* oV = outV + (long long)bn * (L_LEN * H_NUM * E_DIM) + h * E_DIM + e;

#pragma unroll 4
        for (int t = t0; t < t0 + 48; t++) {
            int r0 = t + d0; if (r0 >= 96) r0 -= 96;
            int r1 = t + d1; if (r1 >= 96) r1 -= 96;
            int r2 = t + d2; if (r2 >= 96) r2 -= 96;
            int r3 = t + d3; if (r3 >= 96) r3 -= 96;
            const float s = w0 * vf[r0 * 64 + e] + w1 * vf[r1 * 64 + e]
                          + w2 * vf[r2 * 64 + e] + w3 * vf[r3 * 64 + e];
            oV[(long long)t * (H_NUM * E_DIM)] = s;
        }
    }
}

extern "C" void kernel_launch(void* const* d_in, const int* in_sizes, int n_in,
                              void* d_out, int out_size) {
    const float* q = (const float*)d_in[0];
    const float* k = (const float*)d_in[1];
    const float* v = (const float*)d_in[2];
    float* out  = (float*)d_out;
    // Reference returns (V, corr_transposed): write both when out buffer holds both.
    float* outC = (out_size >= 2 * TOT) ? (out + TOT) : nullptr;

    cudaFuncSetAttribute(autocorr_kernel,
                         cudaFuncAttributeMaxDynamicSharedMemorySize, SMEM_BYTES);
    autocorr_kernel<<<NBN * H_NUM, THREADS, SMEM_BYTES>>>(q, k, v, out, outC);
}

// round 14
// speedup vs baseline: 1.0678x; 1.0300x over previous
#include <cuda_runtime.h>
#include <math.h>

// Problem constants: B=4, N=207, L=96, H=8, E=64
#define L_LEN   96
#define H_NUM   8
#define E_DIM   64
#define NBN     828            // B*N
#define TOT     40697856       // B*N*L*H*E
#define THREADS 128
#define TAU_PER 24             // tau values per thread (4 groups of 24 = 96)

// smem: k_ext only: 192 rows x 32 f32x2 = 48KB. (q read via LDG / L1.)
#define SMEM_ULL   6144
#define SMEM_BYTES (SMEM_ULL * 8)      // 49152 bytes -> 4 blocks/SM

// Packed fp32x2 FMA (Blackwell sm_100+): one instruction, two fp32 FMAs.
__device__ __forceinline__ unsigned long long fma2(unsigned long long a,
                                                   unsigned long long b,
                                                   unsigned long long c) {
    unsigned long long d;
    asm("fma.rn.f32x2 %0, %1, %2, %3;" : "=l"(d) : "l"(a), "l"(b), "l"(c));
    return d;
}
__device__ __forceinline__ float lo2(unsigned long long a) {
    return __uint_as_float((unsigned int)(a & 0xffffffffull));
}
__device__ __forceinline__ float hi2(unsigned long long a) {
    return __uint_as_float((unsigned int)(a >> 32));
}

// ---- Packed sortable key: [ordered-float (25 high bits) | (95 - tau) in low 7] ----
// Ordered transform: unsigned compare order == float value order.
// Low 7 mantissa bits replaced by (95 - tau): exact ties resolve to LOWER tau
// (matches top_k first-occurrence); value perturbation <= 2^-17 rel (tol 1e-3).
__device__ __forceinline__ unsigned key_of(float v, int tau) {
    unsigned b = __float_as_uint(v);
    unsigned o = b ^ (unsigned)(((int)b >> 31) | (int)0x80000000);
    return (o & 0xFFFFFF80u) | (unsigned)(95 - tau);
}
__device__ __forceinline__ float val_of(unsigned key) {
    unsigned u = key & 0xFFFFFF80u;
    unsigned b = u ^ (((int)u < 0) ? 0x80000000u : 0xFFFFFFFFu);
    return __uint_as_float(b);
}
__device__ __forceinline__ int tau_of(unsigned key) {
    return 95 - (int)(key & 127u);
}
// Insert key into descending sorted-4 via pure min/max network (IMNMX only).
__device__ __forceinline__ void insk(unsigned k, unsigned* s) {
    unsigned x = k;
#pragma unroll
    for (int i = 0; i < 4; i++) {
        unsigned hi = (s[i] > x) ? s[i] : x;
        unsigned lo = (s[i] > x) ? x : s[i];
        s[i] = hi; x = lo;
    }
}

__global__ __launch_bounds__(THREADS, 4)
void autocorr_kernel(const float* __restrict__ gq,
                     const float* __restrict__ gk,
                     const float* __restrict__ gv,
                     float* __restrict__ outV,
                     float* __restrict__ outC) {
    extern __shared__ unsigned long long smem[];
    unsigned long long* sm_k = smem;   // [idx][pair] : 192 x 32 f32x2 (k duplicated, wrap-free)

    const int tid  = threadIdx.x;
    const int pair = tid & 31;     // e-pair: e = 2*pair, 2*pair+1
    const int grp  = tid >> 5;     // tau group 0..3
    const int bn   = blockIdx.x >> 3;
    const int h    = blockIdx.x & 7;

    // Base offset in f32x2 units for this (bn, h): layout [bn][l][h][e]
    const long long base2 = (long long)bn * (L_LEN * H_NUM * E_DIM / 2) + h * (E_DIM / 2);
    const unsigned long long* q2 = (const unsigned long long*)gq + base2;
    const unsigned long long* k2 = (const unsigned long long*)gk + base2;
    const unsigned long long* v2 = (const unsigned long long*)gv + base2;

    // ---- Phase 0: stage k (duplicated k_ext[j] = k[j mod 96]); prefetch q into L1 ----
    // Block's q footprint = 96 rows * 256B (aligned) = 1536 lines of 128B.
#pragma unroll
    for (int j = 0; j < 12; j++) {
        const char* pf = (const char*)q2 + (size_t)(tid + j * 128) * 128;
        asm volatile("prefetch.global.L1 [%0];" :: "l"(pf));
    }
#pragma unroll 4
    for (int i = tid; i < 96 * 32; i += THREADS) {
        const int l = i >> 5, p = i & 31;
        const unsigned long long kv = k2[(long long)l * 256 + p];
        sm_k[i]        = kv;
        sm_k[i + 3072] = kv;
    }
    __syncthreads();

    // ---- Phase 1: corr[tau] = sum_t q[t] * k_ext[t - tau + 96] ----
    const int tau0 = grp * TAU_PER;
    unsigned long long acc[TAU_PER];
#pragma unroll
    for (int j = 0; j < TAU_PER; j++) acc[j] = 0ull;

    const unsigned long long* qs = q2 + pair;   // global, L1-resident
    const unsigned long long* ks = sm_k + pair;

    for (int t0 = 0; t0 < L_LEN; t0 += 8) {
        unsigned long long qr[8];
#pragma unroll
        for (int tt = 0; tt < 8; tt++) qr[tt] = __ldg(qs + (long long)(t0 + tt) * 256);

        unsigned long long kr[31];
        const int kb = t0 - tau0 + 73;   // in [1, 161]; kb+30 <= 191
#pragma unroll
        for (int j = 0; j < 31; j++) kr[j] = ks[(kb + j) * 32];

#pragma unroll
        for (int tt = 0; tt < 8; tt++) {
#pragma unroll
            for (int d = 0; d < TAU_PER; d++) {
                // k_ext index = kb + (tt + 23 - d) = (t0+tt) - (tau0+d) + 96
                acc[d] = fma2(qr[tt], kr[tt + 23 - d], acc[d]);
            }
        }
    }

    // Write corr to global and track per-channel top-4 as packed keys.
    unsigned sA[4] = {0u, 0u, 0u, 0u};
    unsigned sB[4] = {0u, 0u, 0u, 0u};

    if (outC) {
        unsigned long long* cbase = (unsigned long long*)outC;
        const long long cOff = base2 + pair;   // ((bn*96+tau)*8+h)*32 + pair
#pragma unroll
        for (int j = 0; j < TAU_PER; j++) {
            cbase[cOff + (long long)(tau0 + j) * 256] = acc[j];
        }
    }
#pragma unroll
    for (int j = 0; j < TAU_PER; j++) {
        insk(key_of(lo2(acc[j]), tau0 + j), sA);
        insk(key_of(hi2(acc[j]), tau0 + j), sB);
    }

    __syncthreads();   // all phase-1 LDS reads of sm_k done; safe to alias

    // ---- Phase 2: merge top-4 across tau groups, softmax ----
    // Scratch lives past the 24KB v-staging region (ull rows >= 96):
    unsigned* cand = (unsigned*)smem + 6144;   // [grp][e][4] keys : 4KB
    float*    wts  = (float*)((unsigned*)smem + 7168);   // [e][4]
    int*      dly  = (int*)  ((unsigned*)smem + 7424);   // [e][4]
    {
        const int e0 = 2 * pair, e1 = e0 + 1;
#pragma unroll
        for (int s = 0; s < 4; s++) {
            cand[(grp * 64 + e0) * 4 + s] = sA[s];
            cand[(grp * 64 + e1) * 4 + s] = sB[s];
        }
    }
    __syncthreads();

    if (tid < 64) {
        unsigned s[4] = {0u, 0u, 0u, 0u};
#pragma unroll
        for (int g = 0; g < 4; g++)
#pragma unroll
            for (int j = 0; j < 4; j++)
                insk(cand[(g * 64 + tid) * 4 + j], s);

        const float m = val_of(s[0]);
        float ex[4], sum = 0.f;
#pragma unroll
        for (int j = 0; j < 4; j++) { ex[j] = expf(val_of(s[j]) - m); sum += ex[j]; }
        const float inv = 1.f / sum;
#pragma unroll
        for (int j = 0; j < 4; j++) { wts[tid * 4 + j] = ex[j] * inv; dly[tid * 4 + j] = tau_of(s[j]); }
    }

    // All threads stage v into sm rows 0..95 (does not touch cand/wts region).
#pragma unroll 4
    for (int i = tid; i < 96 * 32; i += THREADS) {
        const int l = i >> 5, p = i & 31;
        sm_k[i] = v2[(long long)l * 256 + p];
    }
    __syncthreads();

    // ---- Phase 3: V[t] = sum_i w_i * v[(t + delay_i) mod 96] ----
    {
        const int e  = tid & 63;
        const int t0 = (tid >> 6) * 48;
        const float w0 = wts[e * 4 + 0], w1 = wts[e * 4 + 1];
        const float w2 = wts[e * 4 + 2], w3 = wts[e * 4 + 3];
        const int   d0 = dly[e * 4 + 0], d1 = dly[e * 4 + 1];
        const int   d2 = dly[e * 4 + 2], d3 = dly[e * 4 + 3];
        const float* vf = (const float*)sm_k;   // scalar view: [l*64 + e]
        float* oV = outV + (long long)bn * (L_LEN * H_NUM * E_DIM) + h * E_DIM + e;

#pragma unroll 4
        for (int t = t0; t < t0 + 48; t++) {
            int r0 = t + d0; if (r0 >= 96) r0 -= 96;
            int r1 = t + d1; if (r1 >= 96) r1 -= 96;
            int r2 = t + d2; if (r2 >= 96) r2 -= 96;
            int r3 = t + d3; if (r3 >= 96) r3 -= 96;
            const float s = w0 * vf[r0 * 64 + e] + w1 * vf[r1 * 64 + e]
                          + w2 * vf[r2 * 64 + e] + w3 * vf[r3 * 64 + e];
            oV[(long long)t * (H_NUM * E_DIM)] = s;
        }
    }
}

extern "C" void kernel_launch(void* const* d_in, const int* in_sizes, int n_in,
                              void* d_out, int out_size) {
    const float* q = (const float*)d_in[0];
    const float* k = (const float*)d_in[1];
    const float* v = (const float*)d_in[2];
    float* out  = (float*)d_out;
    // Reference returns (V, corr_transposed): write both when out buffer holds both.
    float* outC = (out_size >= 2 * TOT) ? (out + TOT) : nullptr;

    cudaFuncSetAttribute(autocorr_kernel,
                         cudaFuncAttributeMaxDynamicSharedMemorySize, SMEM_BYTES);
    autocorr_kernel<<<NBN * H_NUM, THREADS, SMEM_BYTES>>>(q, k, v, out, outC);
}

// round 15
// speedup vs baseline: 1.0679x; 1.0001x over previous
#include <cuda_runtime.h>
#include <math.h>

// Problem constants: B=4, N=207, L=96, H=8, E=64
#define L_LEN   96
#define H_NUM   8
#define E_DIM   64
#define NBN     828            // B*N
#define TOT     40697856       // B*N*L*H*E
#define THREADS 128
#define TAU_PER 24             // tau values per thread (4 groups of 24 = 96)

// smem: k_ext only: 192 rows x 32 f32x2 = 48KB. (q read via LDG / L1.)
#define SMEM_ULL   6144
#define SMEM_BYTES (SMEM_ULL * 8)      // 49152 bytes -> 4 blocks/SM

// Packed fp32x2 FMA (Blackwell sm_100+): one instruction, two fp32 FMAs.
__device__ __forceinline__ unsigned long long fma2(unsigned long long a,
                                                   unsigned long long b,
                                                   unsigned long long c) {
    unsigned long long d;
    asm("fma.rn.f32x2 %0, %1, %2, %3;" : "=l"(d) : "l"(a), "l"(b), "l"(c));
    return d;
}
__device__ __forceinline__ float lo2(unsigned long long a) {
    return __uint_as_float((unsigned int)(a & 0xffffffffull));
}
__device__ __forceinline__ float hi2(unsigned long long a) {
    return __uint_as_float((unsigned int)(a >> 32));
}

// ---- Packed sortable key: [ordered-float (25 high bits) | (95 - tau) in low 7] ----
// Ordered transform: unsigned compare order == float value order.
// Low 7 mantissa bits replaced by (95 - tau): exact ties resolve to LOWER tau
// (matches top_k first-occurrence); value perturbation <= 2^-17 rel (tol 1e-3).
__device__ __forceinline__ unsigned key_of(float v, int tau) {
    unsigned b = __float_as_uint(v);
    unsigned o = b ^ (unsigned)(((int)b >> 31) | (int)0x80000000);
    return (o & 0xFFFFFF80u) | (unsigned)(95 - tau);
}
__device__ __forceinline__ float val_of(unsigned key) {
    unsigned u = key & 0xFFFFFF80u;
    unsigned b = u ^ (((int)u < 0) ? 0x80000000u : 0xFFFFFFFFu);
    return __uint_as_float(b);
}
__device__ __forceinline__ int tau_of(unsigned key) {
    return 95 - (int)(key & 127u);
}
// Insert key into descending sorted-4 via pure min/max network (IMNMX only).
__device__ __forceinline__ void insk(unsigned k, unsigned* s) {
    unsigned x = k;
#pragma unroll
    for (int i = 0; i < 4; i++) {
        unsigned hi = (s[i] > x) ? s[i] : x;
        unsigned lo = (s[i] > x) ? x : s[i];
        s[i] = hi; x = lo;
    }
}

__global__ __launch_bounds__(THREADS, 4)
void autocorr_kernel(const float* __restrict__ gq,
                     const float* __restrict__ gk,
                     const float* __restrict__ gv,
                     float* __restrict__ outV,
                     float* __restrict__ outC) {
    extern __shared__ unsigned long long smem[];
    unsigned long long* sm_k = smem;   // [idx][pair] : 192 x 32 f32x2 (k duplicated, wrap-free)

    const int tid  = threadIdx.x;
    const int pair = tid & 31;     // e-pair: e = 2*pair, 2*pair+1
    const int grp  = tid >> 5;     // tau group 0..3
    const int bn   = blockIdx.x >> 3;
    const int h    = blockIdx.x & 7;

    // Base offset in f32x2 units for this (bn, h): layout [bn][l][h][e]
    const long long base2 = (long long)bn * (L_LEN * H_NUM * E_DIM / 2) + h * (E_DIM / 2);
    const unsigned long long* q2 = (const unsigned long long*)gq + base2;
    const unsigned long long* k2 = (const unsigned long long*)gk + base2;
    const unsigned long long* v2 = (const unsigned long long*)gv + base2;

    // ---- Phase 0: stage k (duplicated k_ext[j] = k[j mod 96]); prefetch q into L1 ----
    // Block's q footprint = 96 rows * 256B (aligned) = 1536 lines of 128B.
#pragma unroll
    for (int j = 0; j < 12; j++) {
        const char* pf = (const char*)q2 + (size_t)(tid + j * 128) * 128;
        asm volatile("prefetch.global.L1 [%0];" :: "l"(pf));
    }
#pragma unroll 4
    for (int i = tid; i < 96 * 32; i += THREADS) {
        const int l = i >> 5, p = i & 31;
        const unsigned long long kv = k2[(long long)l * 256 + p];
        sm_k[i]        = kv;
        sm_k[i + 3072] = kv;
    }
    __syncthreads();

    // ---- Phase 1: corr[tau] = sum_t q[t] * k_ext[t - tau + 96] ----
    const int tau0 = grp * TAU_PER;
    unsigned long long acc[TAU_PER];
#pragma unroll
    for (int j = 0; j < TAU_PER; j++) acc[j] = 0ull;

    const unsigned long long* qs = q2 + pair;   // global, L1-resident
    const unsigned long long* ks = sm_k + pair;

    for (int t0 = 0; t0 < L_LEN; t0 += 8) {
        unsigned long long qr[8];
#pragma unroll
        for (int tt = 0; tt < 8; tt++) qr[tt] = __ldg(qs + (long long)(t0 + tt) * 256);

        unsigned long long kr[31];
        const int kb = t0 - tau0 + 73;   // in [1, 161]; kb+30 <= 191
#pragma unroll
        for (int j = 0; j < 31; j++) kr[j] = ks[(kb + j) * 32];

#pragma unroll
        for (int tt = 0; tt < 8; tt++) {
#pragma unroll
            for (int d = 0; d < TAU_PER; d++) {
                // k_ext index = kb + (tt + 23 - d) = (t0+tt) - (tau0+d) + 96
                acc[d] = fma2(qr[tt], kr[tt + 23 - d], acc[d]);
            }
        }
    }

    // Write corr to global and track per-channel top-4 as packed keys.
    unsigned sA[4] = {0u, 0u, 0u, 0u};
    unsigned sB[4] = {0u, 0u, 0u, 0u};

    if (outC) {
        unsigned long long* cbase = (unsigned long long*)outC;
        const long long cOff = base2 + pair;   // ((bn*96+tau)*8+h)*32 + pair
#pragma unroll
        for (int j = 0; j < TAU_PER; j++) {
            cbase[cOff + (long long)(tau0 + j) * 256] = acc[j];
        }
    }
#pragma unroll
    for (int j = 0; j < TAU_PER; j++) {
        insk(key_of(lo2(acc[j]), tau0 + j), sA);
        insk(key_of(hi2(acc[j]), tau0 + j), sB);
    }

    __syncthreads();   // all phase-1 LDS reads of sm_k done; safe to alias

    // ---- Phase 2: merge top-4 across tau groups, softmax ----
    // Scratch lives past the 24KB v-staging region (ull rows >= 96):
    unsigned* cand = (unsigned*)smem + 6144;   // [grp][e][4] keys : 4KB
    float*    wts  = (float*)((unsigned*)smem + 7168);   // [e][4]
    int*      dly  = (int*)  ((unsigned*)smem + 7424);   // [e][4]
    {
        const int e0 = 2 * pair, e1 = e0 + 1;
#pragma unroll
        for (int s = 0; s < 4; s++) {
            cand[(grp * 64 + e0) * 4 + s] = sA[s];
            cand[(grp * 64 + e1) * 4 + s] = sB[s];
        }
    }
    __syncthreads();

    if (tid < 64) {
        unsigned s[4] = {0u, 0u, 0u, 0u};
#pragma unroll
        for (int g = 0; g < 4; g++)
#pragma unroll
            for (int j = 0; j < 4; j++)
                insk(cand[(g * 64 + tid) * 4 + j], s);

        const float m = val_of(s[0]);
        float ex[4], sum = 0.f;
#pragma unroll
        for (int j = 0; j < 4; j++) { ex[j] = expf(val_of(s[j]) - m); sum += ex[j]; }
        const float inv = 1.f / sum;
#pragma unroll
        for (int j = 0; j < 4; j++) { wts[tid * 4 + j] = ex[j] * inv; dly[tid * 4 + j] = tau_of(s[j]); }
    }

    // All threads stage v into sm rows 0..95 (does not touch cand/wts region).
#pragma unroll 4
    for (int i = tid; i < 96 * 32; i += THREADS) {
        const int l = i >> 5, p = i & 31;
        sm_k[i] = v2[(long long)l * 256 + p];
    }
    __syncthreads();

    // ---- Phase 3: V[t] = sum_i w_i * v[(t + delay_i) mod 96] ----
    {
        const int e  = tid & 63;
        const int t0 = (tid >> 6) * 48;
        const float w0 = wts[e * 4 + 0], w1 = wts[e * 4 + 1];
        const float w2 = wts[e * 4 + 2], w3 = wts[e * 4 + 3];
        const int   d0 = dly[e * 4 + 0], d1 = dly[e * 4 + 1];
        const int   d2 = dly[e * 4 + 2], d3 = dly[e * 4 + 3];
        const float* vf = (const float*)sm_k;   // scalar view: [l*64 + e]
        float* oV = outV + (long long)bn * (L_LEN * H_NUM * E_DIM) + h * E_DIM + e;

#pragma unroll 4
        for (int t = t0; t < t0 + 48; t++) {
            int r0 = t + d0; if (r0 >= 96) r0 -= 96;
            int r1 = t + d1; if (r1 >= 96) r1 -= 96;
            int r2 = t + d2; if (r2 >= 96) r2 -= 96;
            int r3 = t + d3; if (r3 >= 96) r3 -= 96;
            const float s = w0 * vf[r0 * 64 + e] + w1 * vf[r1 * 64 + e]
                          + w2 * vf[r2 * 64 + e] + w3 * vf[r3 * 64 + e];
            oV[(long long)t * (H_NUM * E_DIM)] = s;
        }
    }
}

extern "C" void kernel_launch(void* const* d_in, const int* in_sizes, int n_in,
                              void* d_out, int out_size) {
    const float* q = (const float*)d_in[0];
    const float* k = (const float*)d_in[1];
    const float* v = (const float*)d_in[2];
    float* out  = (float*)d_out;
    // Reference returns (V, corr_transposed): write both when out buffer holds both.
    float* outC = (out_size >= 2 * TOT) ? (out + TOT) : nullptr;

    cudaFuncSetAttribute(autocorr_kernel,
                         cudaFuncAttributeMaxDynamicSharedMemorySize, SMEM_BYTES);
    autocorr_kernel<<<NBN * H_NUM, THREADS, SMEM_BYTES>>>(q, k, v, out, outC);
}